// round 2
// baseline (speedup 1.0000x reference)
#include <cuda_runtime.h>
#include <math.h>

// Problem constants (from reference): x[B,T], a/b/c/w[H], e[1] -> z[B]
#define TLEN 4096
#define HDIM 512
#define BATCH 64
#define CHUNK 64
#define NCHUNK (TLEN / CHUNK)   // 64 blocks

// Scratch (no allocations allowed -> __device__ globals)
__device__ double g_K[TLEN];
__device__ double g_z0;

// Kernel 1: build K[t] = sum_h (w_h*b_h) * a_h^(T-1-t), and z0 = sum_h w_h*c_h*(1-a^T)/(1-a).
// Grid: NCHUNK blocks x HDIM threads. Block bi handles exponents s in [bi*CHUNK, bi*CHUNK+64).
// Each thread (one h) seeds p = wb * a^s0 via fp64 exp, then runs the geometric
// recurrence p *= a (64 dependent DMULs), warp-reducing across h each step.
__global__ __launch_bounds__(HDIM) void build_K_kernel(
    const float* __restrict__ a, const float* __restrict__ b,
    const float* __restrict__ c, const float* __restrict__ w)
{
    __shared__ double part[16][CHUNK];   // per-warp partial sums, 8 KB
    const int h    = threadIdx.x;
    const int warp = h >> 5;
    const int lane = h & 31;

    const double ad = (double)a[h];
    const double la = log(ad);
    const double wb = (double)w[h] * (double)b[h];

    const int s0 = blockIdx.x * CHUNK;
    double p = wb * exp(la * (double)s0);

    #pragma unroll 4
    for (int i = 0; i < CHUNK; i++) {
        double v = p;
        #pragma unroll
        for (int off = 16; off; off >>= 1)
            v += __shfl_down_sync(0xffffffffu, v, off);
        if (lane == 0) part[warp][i] = v;
        p *= ad;                          // dependent fp64 chain (64 x ~47cyc)
    }
    __syncthreads();

    // Threads 0..63 finalize one t each: sum 16 warp partials.
    if (h < CHUNK) {
        double s = 0.0;
        #pragma unroll
        for (int wg = 0; wg < 16; wg++) s += part[wg][h];
        // exponent s = s0 + h corresponds to t = T-1-s
        g_K[TLEN - 1 - (s0 + h)] = s;
    }

    // Block 0 additionally computes the batch-independent constant z0.
    if (blockIdx.x == 0) {
        __shared__ double zpart[16];
        const double aT  = exp(la * (double)TLEN);
        const double geo = (1.0 - aT) / (1.0 - ad);
        double v = (double)w[h] * (double)c[h] * geo;
        #pragma unroll
        for (int off = 16; off; off >>= 1)
            v += __shfl_down_sync(0xffffffffu, v, off);
        if (lane == 0) zpart[warp] = v;
        __syncthreads();
        if (h == 0) {
            double s = 0.0;
            #pragma unroll
            for (int i = 0; i < 16; i++) s += zpart[i];
            g_z0 = s;
        }
    }
}

// Kernel 2: z[row] = dot(x[row,:], K) + z0 + e. One block per batch row.
__global__ __launch_bounds__(256) void dot_kernel(
    const float* __restrict__ x, const float* __restrict__ e,
    float* __restrict__ out)
{
    const int row = blockIdx.x;
    const int tid = threadIdx.x;
    const float4* xr = (const float4*)(x + (size_t)row * TLEN);

    double acc = 0.0;
    // TLEN/4 = 1024 float4 elements, 256 threads -> 4 iterations
    #pragma unroll
    for (int j = tid; j < TLEN / 4; j += 256) {
        float4 xv = xr[j];
        const int t = j * 4;
        acc += (double)xv.x * g_K[t + 0];
        acc += (double)xv.y * g_K[t + 1];
        acc += (double)xv.z * g_K[t + 2];
        acc += (double)xv.w * g_K[t + 3];
    }
    #pragma unroll
    for (int off = 16; off; off >>= 1)
        acc += __shfl_down_sync(0xffffffffu, acc, off);

    __shared__ double s[8];
    const int warp = tid >> 5, lane = tid & 31;
    if (lane == 0) s[warp] = acc;
    __syncthreads();
    if (tid == 0) {
        double t = 0.0;
        #pragma unroll
        for (int i = 0; i < 8; i++) t += s[i];
        out[row] = (float)(t + g_z0 + (double)e[0]);
    }
}

extern "C" void kernel_launch(void* const* d_in, const int* in_sizes, int n_in,
                              void* d_out, int out_size)
{
    const float* x = (const float*)d_in[0];   // [B, T]
    const float* a = (const float*)d_in[1];   // [H]
    const float* b = (const float*)d_in[2];   // [H]
    const float* c = (const float*)d_in[3];   // [H]
    const float* w = (const float*)d_in[4];   // [H]
    const float* e = (const float*)d_in[5];   // [1]
    float* out = (float*)d_out;               // [B]

    build_K_kernel<<<NCHUNK, HDIM>>>(a, b, c, w);
    dot_kernel<<<BATCH, 256>>>(x, e, out);
}

// round 3
// speedup vs baseline: 6.9584x; 6.9584x over previous
#include <cuda_runtime.h>
#include <math.h>

// z[b] = sum_t x[b,t]*K[t] + z0 + e, with
// K[t]  = sum_h w_h*b_h*a_h^(T-1-t)
// z0    = sum_h w_h*c_h*(1-a_h^T)/(1-a_h)
#define TLEN 4096
#define HDIM 512
#define BATCH 64
#define CHUNK 16
#define NCHUNK (TLEN / CHUNK)   // 256 blocks
#define SEG 4                   // dot segments per batch row

// Scratch (no allocations allowed -> __device__ globals)
__device__ __align__(16) float g_K[TLEN];
__device__ double g_z0;
__device__ float g_part[BATCH * SEG];

// ---- double-float (two-float) arithmetic: all fp32, ~1e-13 relative error ----
struct df2 { float hi, lo; };

__device__ __forceinline__ df2 df_mul(df2 x, df2 y) {
    float p = x.hi * y.hi;
    float e = fmaf(x.hi, y.hi, -p);     // exact product tail (TwoProdFMA)
    e = fmaf(x.hi, y.lo, e);
    e = fmaf(x.lo, y.hi, e);
    float s  = p + e;                   // fast two-sum renorm (|p| >= |e|)
    float lo = (p - s) + e;
    df2 r; r.hi = s; r.lo = lo; return r;
}

// Kernel 1: K[t] for t-chunk of 16 per block, seeds via df binary powering.
// No fp64, no transcendentals.
__global__ __launch_bounds__(HDIM) void build_K_kernel(
    const float* __restrict__ a, const float* __restrict__ b,
    const float* __restrict__ c, const float* __restrict__ w)
{
    __shared__ float part[CHUNK][HDIM];   // 16*512*4 = 32 KB
    const int h = threadIdx.x;
    const int j = blockIdx.x;             // exponent base s0 = 16*j

    const float af = a[h];

    // a^16 via 4 df squarings
    df2 base; base.hi = af; base.lo = 0.0f;
    #pragma unroll
    for (int k = 0; k < 4; k++) base = df_mul(base, base);
    const df2 a16 = base;

    // seed = (a^16)^j via binary powering (j < 256 -> <= 8 iters, uniform per block)
    df2 res; res.hi = 1.0f; res.lo = 0.0f;
    unsigned jj = (unsigned)j;
    while (jj) {
        if (jj & 1u) res = df_mul(res, base);
        base = df_mul(base, base);
        jj >>= 1;
    }

    const float wb = w[h] * b[h];
    float p = wb * (res.hi + res.lo);     // wb * a^(16j)

    // 16-step fp32 geometric recurrence, stash each step into smem
    #pragma unroll
    for (int i = 0; i < CHUNK; i++) {
        part[i][h] = p;
        p *= af;
    }
    __syncthreads();

    // Reduce across h: warp i handles t-offset i (16 warps = 16 offsets)
    const int warp = h >> 5, lane = h & 31;
    float s = 0.0f;
    #pragma unroll
    for (int k = 0; k < HDIM / 32; k++) s += part[warp][lane + 32 * k];
    #pragma unroll
    for (int off = 16; off; off >>= 1) s += __shfl_down_sync(0xffffffffu, s, off);
    if (lane == 0) g_K[TLEN - 1 - (j * CHUNK + warp)] = s;

    // Block 0: z0 = sum_h w*c*(1-a^T)/(1-a); a^4096 = (a^16)^256 by 8 df squarings
    if (j == 0) {
        df2 t = a16;
        #pragma unroll
        for (int k = 0; k < 8; k++) t = df_mul(t, t);
        const float aT  = t.hi + t.lo;
        const float geo = (1.0f - aT) / (1.0f - af);   // 1-af exact (Sterbenz)
        float term = w[h] * c[h] * geo;
        #pragma unroll
        for (int off = 16; off; off >>= 1)
            term += __shfl_down_sync(0xffffffffu, term, off);
        __shared__ float zp[16];
        if (lane == 0) zp[warp] = term;
        __syncthreads();
        if (h == 0) {
            double sz = 0.0;
            #pragma unroll
            for (int i = 0; i < 16; i++) sz += (double)zp[i];
            g_z0 = sz;
        }
    }
}

// Kernel 2: partial dots. 256 blocks = (row, seg); each block covers 1024 t's,
// one float4 per thread.
__global__ __launch_bounds__(256) void dotp_kernel(const float* __restrict__ x)
{
    const int row = blockIdx.x >> 2;
    const int seg = blockIdx.x & 3;
    const int tid = threadIdx.x;
    const int t0  = seg * (TLEN / SEG);           // 1024

    const float4 xv = ((const float4*)(x + (size_t)row * TLEN + t0))[tid];
    const float4 kv = ((const float4*)(g_K + t0))[tid];

    float s = xv.x * kv.x + xv.y * kv.y + xv.z * kv.z + xv.w * kv.w;
    #pragma unroll
    for (int off = 16; off; off >>= 1) s += __shfl_down_sync(0xffffffffu, s, off);

    __shared__ float sp[8];
    const int warp = tid >> 5, lane = tid & 31;
    if (lane == 0) sp[warp] = s;
    __syncthreads();
    if (tid == 0) {
        float t = 0.0f;
        #pragma unroll
        for (int i = 0; i < 8; i++) t += sp[i];
        g_part[blockIdx.x] = t;
    }
}

// Kernel 3: combine partials + z0 + e.
__global__ void final_kernel(const float* __restrict__ e, float* __restrict__ out)
{
    const int r = threadIdx.x;   // 64 threads
    double s = (double)g_part[r * SEG + 0] + (double)g_part[r * SEG + 1]
             + (double)g_part[r * SEG + 2] + (double)g_part[r * SEG + 3];
    out[r] = (float)(s + g_z0 + (double)e[0]);
}

extern "C" void kernel_launch(void* const* d_in, const int* in_sizes, int n_in,
                              void* d_out, int out_size)
{
    const float* x = (const float*)d_in[0];   // [B, T]
    const float* a = (const float*)d_in[1];   // [H]
    const float* b = (const float*)d_in[2];   // [H]
    const float* c = (const float*)d_in[3];   // [H]
    const float* w = (const float*)d_in[4];   // [H]
    const float* e = (const float*)d_in[5];   // [1]
    float* out = (float*)d_out;               // [B]

    build_K_kernel<<<NCHUNK, HDIM>>>(a, b, c, w);
    dotp_kernel<<<BATCH * SEG, 256>>>(x);
    final_kernel<<<1, BATCH>>>(e, out);
}